// round 1
// baseline (speedup 1.0000x reference)
#include <cuda_runtime.h>
#include <math.h>

// ---------------- problem constants ----------------
#define NN   16384
#define MM   65536
#define E1N  131072
#define E2N  131072
#define FF   16384
#define ENCD 512
#define DECD 256
#define HCN  8
#define HIDN 1365
#define HIDP 1408   // padded hidden (multiple of 128)

// ---------------- scratch (device globals; no allocation) ----------------
static __device__ float s_root_ctx[NN * DECD];
static __device__ float s_a_src[MM * HCN];
static __device__ float s_a_tgt[NN * HCN];
static __device__ float s_fb_vals[(size_t)MM * ENCD];
static __device__ float s_w1[E1N * HCN];
static __device__ float s_den1[NN * HCN];
static __device__ float s_agg1[(size_t)NN * ENCD];
static __device__ float s_x1[(size_t)NN * ENCD];
static __device__ float s_q[(size_t)NN * ENCD];
static __device__ float s_k[(size_t)NN * ENCD];
static __device__ float s_v[(size_t)NN * ENCD];
static __device__ float s_w2[E2N * HCN];
static __device__ float s_den2[NN * HCN];
static __device__ float s_agg2[(size_t)NN * ENCD];
static __device__ float s_x2[(size_t)NN * ENCD];
static __device__ float s_gate[(size_t)NN * HIDP];
static __device__ float s_up[(size_t)NN * HIDP];
static __device__ float s_wgate_p[512 * HIDP];
static __device__ float s_wup_p[512 * HIDP];
static __device__ float s_wout_p[HIDP * 512];
static __device__ float s_o[(size_t)NN * ENCD];

__device__ __forceinline__ float4 ld4(const float* p) {
    return *reinterpret_cast<const float4*>(p);
}

// ---------------- generic 128x128x16 SGEMM, 256 threads, 8x8 per thread ----------------
// EPI: 0 = C = acc + bias        (C0, ldc=Nc)
//      1 = qkv de-interleave     (C0=q, C1=k, C2=v, each [rows,512] head-major)
//      2 = fringe                (C0 = (acc+bias) * emul, ldc=Nc)
// GATHER: A row r is rowidx[r]
template<int EPI, bool GATHER>
__global__ __launch_bounds__(256, 2)
void sgemm128(const float* __restrict__ A, const float* __restrict__ B,
              const float* __restrict__ bias,
              float* __restrict__ C0, float* __restrict__ C1, float* __restrict__ C2,
              const float* __restrict__ emul, const int* __restrict__ rowidx,
              int Nc, int K)
{
    __shared__ float As[16][128];
    __shared__ float Bs[16][128];

    const int tid = threadIdx.x;
    const int tx  = tid & 15;
    const int ty  = tid >> 4;
    const long bn = (long)blockIdx.x * 128;
    const long bm = (long)blockIdx.y * 128;

    const int aRow = tid >> 2;          // 0..63
    const int aCol = (tid & 3) << 2;    // 0,4,8,12
    const int bRow = tid >> 5;          // 0..7
    const int bCol = (tid & 31) << 2;   // 0..124

    const float *Ar0, *Ar1;
    {
        long r0 = bm + aRow, r1 = r0 + 64;
        long g0 = GATHER ? (long)rowidx[r0] : r0;
        long g1 = GATHER ? (long)rowidx[r1] : r1;
        Ar0 = A + g0 * (long)K;
        Ar1 = A + g1 * (long)K;
    }

    float acc[8][8];
    #pragma unroll
    for (int m = 0; m < 8; m++)
        #pragma unroll
        for (int n2 = 0; n2 < 8; n2++) acc[m][n2] = 0.f;

    const long gcol = bn + bCol;

    for (int kt = 0; kt < K; kt += 16) {
        float4 a0 = ld4(Ar0 + kt + aCol);
        float4 a1 = ld4(Ar1 + kt + aCol);
        As[aCol + 0][aRow] = a0.x; As[aCol + 1][aRow] = a0.y;
        As[aCol + 2][aRow] = a0.z; As[aCol + 3][aRow] = a0.w;
        As[aCol + 0][aRow + 64] = a1.x; As[aCol + 1][aRow + 64] = a1.y;
        As[aCol + 2][aRow + 64] = a1.z; As[aCol + 3][aRow + 64] = a1.w;

        float4 b0, b1;
        if (gcol + 3 < Nc) {
            b0 = ld4(B + (long)(kt + bRow) * Nc + gcol);
            b1 = ld4(B + (long)(kt + bRow + 8) * Nc + gcol);
        } else {
            float t0[4], t1[4];
            #pragma unroll
            for (int e = 0; e < 4; e++) {
                bool ok = (gcol + e) < Nc;
                t0[e] = ok ? B[(long)(kt + bRow) * Nc + gcol + e] : 0.f;
                t1[e] = ok ? B[(long)(kt + bRow + 8) * Nc + gcol + e] : 0.f;
            }
            b0 = make_float4(t0[0], t0[1], t0[2], t0[3]);
            b1 = make_float4(t1[0], t1[1], t1[2], t1[3]);
        }
        *reinterpret_cast<float4*>(&Bs[bRow][bCol])     = b0;
        *reinterpret_cast<float4*>(&Bs[bRow + 8][bCol]) = b1;

        __syncthreads();

        #pragma unroll
        for (int kk = 0; kk < 16; kk++) {
            float4 aA = ld4(&As[kk][ty * 8]);
            float4 aB = ld4(&As[kk][ty * 8 + 4]);
            float4 bA = ld4(&Bs[kk][tx * 8]);
            float4 bB = ld4(&Bs[kk][tx * 8 + 4]);
            float a[8] = {aA.x, aA.y, aA.z, aA.w, aB.x, aB.y, aB.z, aB.w};
            float b[8] = {bA.x, bA.y, bA.z, bA.w, bB.x, bB.y, bB.z, bB.w};
            #pragma unroll
            for (int m = 0; m < 8; m++)
                #pragma unroll
                for (int n2 = 0; n2 < 8; n2++)
                    acc[m][n2] += a[m] * b[n2];
        }
        __syncthreads();
    }

    #pragma unroll
    for (int m = 0; m < 8; m++) {
        long row = bm + ty * 8 + m;
        #pragma unroll
        for (int n2 = 0; n2 < 8; n2++) {
            long col = bn + tx * 8 + n2;
            if (col >= Nc) continue;
            float vv = acc[m][n2];
            if (bias) vv += bias[col];
            if (EPI == 0) {
                C0[row * Nc + col] = vv;
            } else if (EPI == 1) {
                int c = (int)col;
                int h = c / 192;
                int r = c % 192;
                int d = r / 3, t = r % 3;
                float* P = (t == 0) ? C0 : ((t == 1) ? C1 : C2);
                P[row * 512 + h * 64 + d] = vv;
            } else {
                C0[row * Nc + col] = vv * emul[row * Nc + col];
            }
        }
    }
}

// ---------------- skinny projection: out[row,0..7] = A[row,:]@W (K=256) ----------------
__global__ void k_proj8(const float* __restrict__ A, const float* __restrict__ W,
                        float* __restrict__ out)
{
    __shared__ float Wsh[256 * 8];
    int t = threadIdx.x; // 256
    for (int idx = t; idx < 2048; idx += 256) Wsh[idx] = W[idx];
    __syncthreads();
    int warp = t >> 5, lane = t & 31;
    long row = (long)blockIdx.x * 8 + warp;
    const float* a = A + row * 256;
    float acc[8] = {0.f,0.f,0.f,0.f,0.f,0.f,0.f,0.f};
    for (int kk = lane; kk < 256; kk += 32) {
        float av = a[kk];
        #pragma unroll
        for (int h = 0; h < 8; h++) acc[h] += av * Wsh[kk * 8 + h];
    }
    #pragma unroll
    for (int h = 0; h < 8; h++)
        #pragma unroll
        for (int off = 16; off; off >>= 1)
            acc[h] += __shfl_xor_sync(0xffffffffu, acc[h], off);
    if (lane == 0) {
        #pragma unroll
        for (int h = 0; h < 8; h++) out[row * 8 + h] = acc[h];
    }
}

// ---------------- edge / elementwise kernels ----------------
__global__ void k_zero(float* p, long n) {
    long i = (long)blockIdx.x * 256 + threadIdx.x;
    if (i < n) p[i] = 0.f;
}

__global__ void k_den1_init(const float* __restrict__ a_tgt, const float* __restrict__ b_attn,
                            float* __restrict__ den1) {
    int i = blockIdx.x * 256 + threadIdx.x; // NN*8
    if (i >= NN * 8) return;
    float s = a_tgt[i] + b_attn[i & 7];
    s = s > 0.f ? s : 0.2f * s;
    den1[i] = expf(s);
}

__global__ void k_agg1_init(const float* __restrict__ root, const float* __restrict__ den1,
                            float* __restrict__ agg1) {
    long i = (long)blockIdx.x * 256 + threadIdx.x; // NN*512
    long n = i >> 9; int c = (int)(i & 511);
    agg1[i] = den1[(n << 3) + (c >> 6)] * root[i];
}

__global__ void k_edge1_scores(const int* __restrict__ ej, const int* __restrict__ ei,
                               const float* __restrict__ a_src, const float* __restrict__ a_tgt,
                               const float* __restrict__ b_attn,
                               float* __restrict__ w1, float* __restrict__ den1) {
    int e = blockIdx.x * 256 + threadIdx.x;
    if (e >= E1N) return;
    int j = ej[e], i = ei[e];
    #pragma unroll
    for (int h = 0; h < 8; h++) {
        float s = a_src[j * 8 + h] + a_tgt[i * 8 + h] + b_attn[h];
        s = s > 0.f ? s : 0.2f * s;
        float w = expf(s);
        w1[e * 8 + h] = w;
        atomicAdd(&den1[i * 8 + h], w);
    }
}

__global__ void k_edge_scatter(const int* __restrict__ ej, const int* __restrict__ ei,
                               const float* __restrict__ w, const float* __restrict__ vals,
                               float* __restrict__ agg) {
    int e = blockIdx.x;
    int t = threadIdx.x; // 128
    __shared__ float w8[8];
    __shared__ int sidx[2];
    if (t == 0) { sidx[0] = ej[e]; sidx[1] = ei[e]; }
    if (t < 8) w8[t] = w[e * 8 + t];
    __syncthreads();
    const float* src = vals + (size_t)sidx[0] * 512;
    float* dst = agg + (size_t)sidx[1] * 512;
    #pragma unroll
    for (int u2 = 0; u2 < 4; u2++) {
        int c = t + u2 * 128;
        atomicAdd(dst + c, w8[c >> 6] * src[c]);
    }
}

__global__ void k_edge2_scores(const float* __restrict__ q, const float* __restrict__ k,
                               const int* __restrict__ sj, const int* __restrict__ si,
                               const float* __restrict__ attr,
                               float* __restrict__ w2, float* __restrict__ den2) {
    int warp = (blockIdx.x * 256 + threadIdx.x) >> 5;
    int lane = threadIdx.x & 31;
    if (warp >= E2N) return;
    int jj = sj[warp], ii = si[warp];
    float a1 = attr[(size_t)warp * 64 + lane];
    float a2 = attr[(size_t)warp * 64 + 32 + lane];
    const float* qr = q + (size_t)ii * 512;
    const float* kr = k + (size_t)jj * 512;
    #pragma unroll
    for (int h = 0; h < 8; h++) {
        float p = qr[h * 64 + lane] * kr[h * 64 + lane] * a1
                + qr[h * 64 + 32 + lane] * kr[h * 64 + 32 + lane] * a2;
        #pragma unroll
        for (int off = 16; off; off >>= 1) p += __shfl_xor_sync(0xffffffffu, p, off);
        if (lane == 0) {
            float w = expf(p * 0.125f);
            w2[warp * 8 + h] = w;
            atomicAdd(&den2[ii * 8 + h], w);
        }
    }
}

// out = rmsnorm(base + (den ? num/den : num), g); den is per (node, head), 0-guarded
__global__ void k_rmsnorm(const float* __restrict__ base, const float* __restrict__ num,
                          const float* __restrict__ den, const float* __restrict__ g,
                          float* __restrict__ out) {
    int n = blockIdx.x;
    int t = threadIdx.x; // 128
    float v[4]; float ss = 0.f;
    #pragma unroll
    for (int u2 = 0; u2 < 4; u2++) {
        int c = t + u2 * 128;
        float a = num[(size_t)n * 512 + c];
        float add;
        if (den) { float d = den[n * 8 + (c >> 6)]; add = (d != 0.f) ? a / d : 0.f; }
        else add = a;
        float val = base[(size_t)n * 512 + c] + add;
        v[u2] = val; ss += val * val;
    }
    #pragma unroll
    for (int off = 16; off; off >>= 1) ss += __shfl_xor_sync(0xffffffffu, ss, off);
    __shared__ float red[4];
    if ((t & 31) == 0) red[t >> 5] = ss;
    __syncthreads();
    float tot = red[0] + red[1] + red[2] + red[3];
    float r = rsqrtf(tot * (1.0f / 512.0f) + 1e-6f);
    #pragma unroll
    for (int u2 = 0; u2 < 4; u2++) {
        int c = t + u2 * 128;
        out[(size_t)n * 512 + c] = v[u2] * r * g[c];
    }
}

__global__ void k_silu(float* __restrict__ g, const float* __restrict__ u, long n) {
    long i = (long)blockIdx.x * 256 + threadIdx.x;
    if (i < n) {
        float x = g[i];
        float s = x / (1.f + expf(-x));
        g[i] = s * u[i];
    }
}

__global__ void k_pad_gateup(const float* __restrict__ W, float* __restrict__ out) {
    int i = blockIdx.x * 256 + threadIdx.x; // 512*1408
    if (i >= 512 * HIDP) return;
    int r = i / HIDP, c = i % HIDP;
    out[i] = (c < HIDN) ? W[r * HIDN + c] : 0.f;
}

__global__ void k_pad_wout(const float* __restrict__ W, float* __restrict__ out) {
    int i = blockIdx.x * 256 + threadIdx.x; // 1408*512
    if (i >= HIDP * 512) return;
    int r = i / 512, c = i % 512;
    out[i] = (r < HIDN) ? W[r * 512 + c] : 0.f;
}

// ---------------- host ----------------
#define SYM(p, s) cudaGetSymbolAddress((void**)&(p), s)

extern "C" void kernel_launch(void* const* d_in, const int* in_sizes, int n_in,
                              void* d_out, int out_size) {
    (void)in_sizes; (void)n_in; (void)out_size;
    const float* root   = (const float*)d_in[0];
    const float* fb     = (const float*)d_in[1];
    const int*   fbi    = (const int*)d_in[2];
    const int*   e1j = fbi;       const int* e1i = fbi + E1N;
    const float* fmaps  = (const float*)d_in[3];
    const int*   r2f    = (const int*)d_in[4];
    const int*   rei    = (const int*)d_in[5];
    const int*   e2j = rei;       const int* e2i = rei + E2N;
    const float* attr   = (const float*)d_in[6];
    const float* W_c2x  = (const float*)d_in[7];
    const float* b_c2x  = (const float*)d_in[8];
    const float* W_x2c  = (const float*)d_in[9];
    const float* b_x2c  = (const float*)d_in[10];
    const float* W_attn = (const float*)d_in[11];
    const float* b_attn = (const float*)d_in[12];
    const float* W_qkv  = (const float*)d_in[13];
    const float* b_qkv  = (const float*)d_in[14];
    const float* W_gate = (const float*)d_in[15];
    const float* W_up   = (const float*)d_in[16];
    const float* W_out  = (const float*)d_in[17];
    const float* W_fr   = (const float*)d_in[18];
    const float* b_fr   = (const float*)d_in[19];
    const float* gn     = (const float*)d_in[20];
    const float* gr     = (const float*)d_in[21];
    const float* gf     = (const float*)d_in[22];

    float* outx = (float*)d_out;
    float* outf = outx + (size_t)NN * ENCD;

    float *p_root_ctx, *p_a_src, *p_a_tgt, *p_fb_vals, *p_w1, *p_den1, *p_agg1, *p_x1;
    float *p_q, *p_k, *p_v, *p_w2, *p_den2, *p_agg2, *p_x2;
    float *p_gate, *p_up, *p_wgp, *p_wup, *p_wop, *p_o;
    SYM(p_root_ctx, s_root_ctx); SYM(p_a_src, s_a_src); SYM(p_a_tgt, s_a_tgt);
    SYM(p_fb_vals, s_fb_vals);   SYM(p_w1, s_w1);       SYM(p_den1, s_den1);
    SYM(p_agg1, s_agg1);         SYM(p_x1, s_x1);
    SYM(p_q, s_q); SYM(p_k, s_k); SYM(p_v, s_v);
    SYM(p_w2, s_w2); SYM(p_den2, s_den2); SYM(p_agg2, s_agg2); SYM(p_x2, s_x2);
    SYM(p_gate, s_gate); SYM(p_up, s_up);
    SYM(p_wgp, s_wgate_p); SYM(p_wup, s_wup_p); SYM(p_wop, s_wout_p);
    SYM(p_o, s_o);

    // ---- HGAT pre-projections ----
    sgemm128<0, false><<<dim3(2, 128), 256>>>(root, W_x2c, b_x2c,
        p_root_ctx, nullptr, nullptr, nullptr, nullptr, DECD, ENCD);
    k_proj8<<<MM / 8, 256>>>(fb, W_attn, p_a_src);
    k_proj8<<<NN / 8, 256>>>(p_root_ctx, W_attn + 256 * 8, p_a_tgt);
    sgemm128<0, false><<<dim3(4, 512), 256>>>(fb, W_c2x, b_c2x,
        p_fb_vals, nullptr, nullptr, nullptr, nullptr, ENCD, DECD);

    // ---- HGAT edge softmax + aggregate ----
    k_den1_init<<<NN * 8 / 256, 256>>>(p_a_tgt, b_attn, p_den1);
    k_agg1_init<<<NN * 512 / 256, 256>>>(root, p_den1, p_agg1);
    k_edge1_scores<<<E1N / 256, 256>>>(e1j, e1i, p_a_src, p_a_tgt, b_attn, p_w1, p_den1);
    k_edge_scatter<<<E1N, 128>>>(e1j, e1i, p_w1, p_fb_vals, p_agg1);
    k_rmsnorm<<<NN, 128>>>(root, p_agg1, p_den1, gn, p_x1);

    // ---- Self-MHA over root graph ----
    sgemm128<1, false><<<dim3(12, 128), 256>>>(p_x1, W_qkv, b_qkv,
        p_q, p_k, p_v, nullptr, nullptr, 1536, ENCD);
    k_zero<<<NN * 8 / 256, 256>>>(p_den2, (long)NN * 8);
    k_zero<<<NN * 512 / 256, 256>>>(p_agg2, (long)NN * 512);
    k_edge2_scores<<<E2N / 8, 256>>>(p_q, p_k, e2j, e2i, attr, p_w2, p_den2);
    k_edge_scatter<<<E2N, 128>>>(e2j, e2i, p_w2, p_v, p_agg2);
    k_rmsnorm<<<NN, 128>>>(p_x1, p_agg2, p_den2, gr, p_x2);

    // ---- SwiGLU FFN ----
    k_pad_gateup<<<(512 * HIDP + 255) / 256, 256>>>(W_gate, p_wgp);
    k_pad_gateup<<<(512 * HIDP + 255) / 256, 256>>>(W_up, p_wup);
    k_pad_wout<<<(HIDP * 512 + 255) / 256, 256>>>(W_out, p_wop);
    sgemm128<0, false><<<dim3(HIDP / 128, 128), 256>>>(p_x2, p_wgp, nullptr,
        p_gate, nullptr, nullptr, nullptr, nullptr, HIDP, ENCD);
    sgemm128<0, false><<<dim3(HIDP / 128, 128), 256>>>(p_x2, p_wup, nullptr,
        p_up, nullptr, nullptr, nullptr, nullptr, HIDP, ENCD);
    k_silu<<<(int)(((long)NN * HIDP + 255) / 256), 256>>>(p_gate, p_up, (long)NN * HIDP);
    sgemm128<0, false><<<dim3(4, 128), 256>>>(p_gate, p_wop, nullptr,
        p_o, nullptr, nullptr, nullptr, nullptr, ENCD, HIDP);
    k_rmsnorm<<<NN, 128>>>(p_x2, p_o, nullptr, gf, outx);

    // ---- fringe decode (gathered rows of x) ----
    sgemm128<2, true><<<dim3(2, 128), 256>>>(outx, W_fr, b_fr,
        outf, nullptr, nullptr, fmaps, r2f, DECD, ENCD);
}

// round 4
// speedup vs baseline: 2.1701x; 2.1701x over previous
#include <cuda_runtime.h>
#include <cuda_bf16.h>
#include <cstdint>
#include <math.h>

// ---------------- problem constants ----------------
#define NN   16384
#define MM   65536
#define E1N  131072
#define E2N  131072
#define ENCD 512
#define DECD 256
#define HCN  8
#define HIDN 1365
#define HIDP 1408

typedef __nv_bfloat16 bf16;

// ---------------- fp32 scratch ----------------
static __device__ float s_root_ctx[NN * DECD];
static __device__ float s_a_src[MM * HCN];
static __device__ float s_a_tgt[NN * HCN];
static __device__ float s_fb_vals[(size_t)MM * ENCD];
static __device__ float s_w1[E1N * HCN];
static __device__ float s_den1[NN * HCN];
static __device__ float s_agg1[(size_t)NN * ENCD];
static __device__ float s_x1[(size_t)NN * ENCD];
static __device__ float s_q[(size_t)NN * ENCD];
static __device__ float s_k[(size_t)NN * ENCD];
static __device__ float s_v[(size_t)NN * ENCD];
static __device__ float s_w2[E2N * HCN];
static __device__ float s_den2[NN * HCN];
static __device__ float s_agg2[(size_t)NN * ENCD];
static __device__ float s_x2[(size_t)NN * ENCD];
static __device__ float s_gate[(size_t)NN * HIDP];
static __device__ float s_up[(size_t)NN * HIDP];
static __device__ float s_o[(size_t)NN * ENCD];

// ---------------- bf16 hi/lo scratch ----------------
static __device__ bf16 s_rbh[(size_t)NN * ENCD],  s_rbl[(size_t)NN * ENCD];
static __device__ bf16 s_fbh[(size_t)MM * DECD],  s_fbl[(size_t)MM * DECD];
static __device__ bf16 s_x1h[(size_t)NN * ENCD],  s_x1l[(size_t)NN * ENCD];
static __device__ bf16 s_x2h[(size_t)NN * ENCD],  s_x2l[(size_t)NN * ENCD];
static __device__ bf16 s_gsh[(size_t)NN * HIDP],  s_gsl[(size_t)NN * HIDP];
static __device__ bf16 s_xfh[(size_t)NN * ENCD],  s_xfl[(size_t)NN * ENCD];
// weights
static __device__ bf16 s_wxh[ENCD * DECD],  s_wxl[ENCD * DECD];      // W_x2c
static __device__ bf16 s_wch[DECD * ENCD],  s_wcl[DECD * ENCD];      // W_c2x
static __device__ bf16 s_wqh[ENCD * 1536],  s_wql[ENCD * 1536];      // W_qkv
static __device__ bf16 s_wgh[ENCD * HIDP],  s_wgl[ENCD * HIDP];      // W_gate pad
static __device__ bf16 s_wuh[ENCD * HIDP],  s_wul[ENCD * HIDP];      // W_up pad
static __device__ bf16 s_woh[HIDP * ENCD],  s_wol[HIDP * ENCD];      // W_out pad
static __device__ bf16 s_wfh[ENCD * DECD],  s_wfl[ENCD * DECD];      // W_fr

__device__ __forceinline__ float4 ld4(const float* p) {
    return *reinterpret_cast<const float4*>(p);
}

__device__ __forceinline__ void split2(float f, bf16& h, bf16& l) {
    h = __float2bfloat16(f);
    l = __float2bfloat16(f - __bfloat162float(h));
}

// ================= baseline-PTX tensor helpers =================
__device__ __forceinline__ uint32_t smem_u32(const void* p) {
    uint32_t a;
    asm("{ .reg .u64 t; cvta.to.shared.u64 t, %1; cvt.u32.u64 %0, t; }" : "=r"(a) : "l"(p));
    return a;
}
#define CP16(dst, src) asm volatile("cp.async.cg.shared.global [%0], [%1], 16;" :: "r"(dst), "l"(src))
#define CP_COMMIT()    asm volatile("cp.async.commit_group;" ::: "memory")
#define CP_WAIT0()     asm volatile("cp.async.wait_group 0;" ::: "memory")

#define LDSMX4(r, a) \
    asm volatile("ldmatrix.sync.aligned.m8n8.x4.shared.b16 {%0,%1,%2,%3}, [%4];" \
        : "=r"((r)[0]), "=r"((r)[1]), "=r"((r)[2]), "=r"((r)[3]) : "r"(a))
#define LDSMX4T(r, a) \
    asm volatile("ldmatrix.sync.aligned.m8n8.x4.trans.shared.b16 {%0,%1,%2,%3}, [%4];" \
        : "=r"((r)[0]), "=r"((r)[1]), "=r"((r)[2]), "=r"((r)[3]) : "r"(a))

#define MMA(d, a, b0, b1) \
    asm volatile("mma.sync.aligned.m16n8k16.row.col.f32.bf16.bf16.f32 " \
        "{%0,%1,%2,%3},{%4,%5,%6,%7},{%8,%9},{%0,%1,%2,%3};" \
        : "+f"((d)[0]), "+f"((d)[1]), "+f"((d)[2]), "+f"((d)[3]) \
        : "r"((a)[0]), "r"((a)[1]), "r"((a)[2]), "r"((a)[3]), "r"(b0), "r"(b1))

// smem byte layout per buffer: AH[128x40] AL BH[32x136] BL
#define OFF_AL 10240
#define OFF_BH 20480
#define OFF_BL 29184
#define BUFB   37888
#define SMEMB  (2 * BUFB)

// ============ split-bf16 HMMA GEMM: C[M,Nc] = (Ahi+Alo)@(Bhi+Blo) (+bias) ============
// EPI: 0 plain, 1 qkv de-interleave, 2 fringe (*emul). GATHER: A row = rowidx[row].
template<int EPI, bool GATHER>
__global__ __launch_bounds__(256)
void hgemm(const bf16* __restrict__ Ahi, const bf16* __restrict__ Alo,
           const bf16* __restrict__ Bhi, const bf16* __restrict__ Blo,
           const float* __restrict__ bias,
           float* __restrict__ C0, float* __restrict__ C1, float* __restrict__ C2,
           const float* __restrict__ emul, const int* __restrict__ rowidx,
           int Nc, int K)
{
    extern __shared__ __align__(16) char smc[];
    const uint32_t smb = smem_u32(smc);
    const int tid  = threadIdx.x;
    const int wid  = tid >> 5;
    const int lane = tid & 31;
    const int warp_m = wid >> 2;   // 0..1
    const int warp_n = wid & 3;    // 0..3
    const long bm = (long)blockIdx.y * 128;
    const long bn = (long)blockIdx.x * 128;

    // ---- per-thread global pointers for cp.async ----
    long g0 = bm + (tid >> 2), g1 = g0 + 64;
    if (GATHER) {
        g0 = (long)rowidx[bm + (tid >> 2)];
        g1 = (long)rowidx[bm + (tid >> 2) + 64];
    }
    const bf16* pAh0 = Ahi + g0 * (long)K + (tid & 3) * 8;
    const bf16* pAl0 = Alo + g0 * (long)K + (tid & 3) * 8;
    const bf16* pAh1 = Ahi + g1 * (long)K + (tid & 3) * 8;
    const bf16* pAl1 = Alo + g1 * (long)K + (tid & 3) * 8;
    const bf16* pBh  = Bhi + (long)(tid >> 4) * Nc + bn + (tid & 15) * 8;
    const bf16* pBl  = Blo + (long)(tid >> 4) * Nc + bn + (tid & 15) * 8;

    const uint32_t dA  = (uint32_t)((tid >> 2) * 80 + (tid & 3) * 16);
    const uint32_t dA2 = dA + 64 * 80;
    const uint32_t dB  = (uint32_t)((tid >> 4) * 272 + (tid & 15) * 16);
    const uint32_t dB2 = dB + 16 * 272;

    float acc[4][4][4];
    #pragma unroll
    for (int a = 0; a < 4; a++)
        #pragma unroll
        for (int b = 0; b < 4; b++)
            #pragma unroll
            for (int c = 0; c < 4; c++) acc[a][b][c] = 0.f;

    const int nch = K >> 5;

    // prologue loads
    {
        const uint32_t base = smb;
        CP16(base + dA,            pAh0);
        CP16(base + OFF_AL + dA,   pAl0);
        CP16(base + dA2,           pAh1);
        CP16(base + OFF_AL + dA2,  pAl1);
        CP16(base + OFF_BH + dB,   pBh);
        CP16(base + OFF_BL + dB,   pBl);
        CP16(base + OFF_BH + dB2,  pBh + 16L * Nc);
        CP16(base + OFF_BL + dB2,  pBl + 16L * Nc);
        CP_COMMIT();
    }

    for (int ch = 0; ch < nch; ch++) {
        CP_WAIT0();
        __syncthreads();
        if (ch + 1 < nch) {
            const int kt = (ch + 1) << 5;
            const uint32_t base = smb + ((ch + 1) & 1) * BUFB;
            CP16(base + dA,           pAh0 + kt);
            CP16(base + OFF_AL + dA,  pAl0 + kt);
            CP16(base + dA2,          pAh1 + kt);
            CP16(base + OFF_AL + dA2, pAl1 + kt);
            const bf16* q0 = pBh + (long)kt * Nc;
            const bf16* q1 = pBl + (long)kt * Nc;
            CP16(base + OFF_BH + dB,  q0);
            CP16(base + OFF_BL + dB,  q1);
            CP16(base + OFF_BH + dB2, q0 + 16L * Nc);
            CP16(base + OFF_BL + dB2, q1 + 16L * Nc);
            CP_COMMIT();
        }
        const uint32_t abase = smb + (ch & 1) * BUFB;
        const uint32_t bbase = abase + OFF_BH;

        #pragma unroll
        for (int ks = 0; ks < 2; ks++) {
            uint32_t ah[4][4], al[4][4];
            #pragma unroll
            for (int mt = 0; mt < 4; mt++) {
                uint32_t ad = abase
                    + (uint32_t)((warp_m * 64 + mt * 16 + (lane & 15)) * 80)
                    + (uint32_t)((ks * 16 + ((lane >> 4) << 3)) << 1);
                LDSMX4(ah[mt], ad);
                LDSMX4(al[mt], ad + OFF_AL);
            }
            uint32_t bh[2][4], bl[2][4];
            #pragma unroll
            for (int p = 0; p < 2; p++) {
                int kk = ks * 16 + (lane & 7) + ((lane >> 3) & 1) * 8;
                int nn = warp_n * 32 + p * 16 + ((lane >> 4) & 1) * 8;
                uint32_t bd = bbase + (uint32_t)(kk * 272 + nn * 2);
                LDSMX4T(bh[p], bd);
                LDSMX4T(bl[p], bd + (OFF_BL - OFF_BH));
            }
            #pragma unroll
            for (int mt = 0; mt < 4; mt++)
                #pragma unroll
                for (int nt = 0; nt < 4; nt++) {
                    const int p = nt >> 1, h = (nt & 1) * 2;
                    MMA(acc[mt][nt], ah[mt], bh[p][h], bh[p][h + 1]);
                    MMA(acc[mt][nt], ah[mt], bl[p][h], bl[p][h + 1]);
                    MMA(acc[mt][nt], al[mt], bh[p][h], bh[p][h + 1]);
                }
        }
        __syncthreads();
    }

    // ---- epilogue ----
    #pragma unroll
    for (int mt = 0; mt < 4; mt++) {
        #pragma unroll
        for (int nt = 0; nt < 4; nt++) {
            long r0 = bm + warp_m * 64 + mt * 16 + (lane >> 2);
            int  c0 = (int)bn + warp_n * 32 + nt * 8 + (lane & 3) * 2;
            #pragma unroll
            for (int half = 0; half < 2; half++) {
                long r = r0 + half * 8;
                float v0 = acc[mt][nt][half * 2 + 0];
                float v1 = acc[mt][nt][half * 2 + 1];
                if (bias) { v0 += bias[c0]; v1 += bias[c0 + 1]; }
                if (EPI == 1) {
                    #pragma unroll
                    for (int e = 0; e < 2; e++) {
                        int gc = c0 + e;
                        float vv = e ? v1 : v0;
                        int h = gc / 192, rr = gc % 192;
                        int d = rr / 3, t = rr % 3;
                        float* P = (t == 0) ? C0 : ((t == 1) ? C1 : C2);
                        P[r * 512 + h * 64 + d] = vv;
                    }
                } else {
                    if (EPI == 2) {
                        v0 *= emul[r * (long)Nc + c0];
                        v1 *= emul[r * (long)Nc + c0 + 1];
                    }
                    float2 o = make_float2(v0, v1);
                    *reinterpret_cast<float2*>(C0 + r * (long)Nc + c0) = o;
                }
            }
        }
    }
}

// ---------------- conversion kernels ----------------
__global__ void k_split(const float* __restrict__ in, bf16* __restrict__ hi,
                        bf16* __restrict__ lo, long n4) {
    long i = (long)blockIdx.x * 256 + threadIdx.x;
    if (i >= n4) return;
    long idx = i * 4;
    float4 v = ld4(in + idx);
    bf16 h[4], l[4];
    split2(v.x, h[0], l[0]); split2(v.y, h[1], l[1]);
    split2(v.z, h[2], l[2]); split2(v.w, h[3], l[3]);
    *reinterpret_cast<uint64_t*>(hi + idx) = *reinterpret_cast<uint64_t*>(h);
    *reinterpret_cast<uint64_t*>(lo + idx) = *reinterpret_cast<uint64_t*>(l);
}

__global__ void k_split_padc(const float* __restrict__ W, bf16* __restrict__ hi,
                             bf16* __restrict__ lo) { // [512,1365] -> [512,1408]
    int i = blockIdx.x * 256 + threadIdx.x;
    if (i >= 512 * HIDP) return;
    int r = i / HIDP, c = i % HIDP;
    float v = (c < HIDN) ? W[r * HIDN + c] : 0.f;
    bf16 h, l; split2(v, h, l);
    hi[i] = h; lo[i] = l;
}

__global__ void k_split_padr(const float* __restrict__ W, bf16* __restrict__ hi,
                             bf16* __restrict__ lo) { // [1365,512] -> [1408,512]
    int i = blockIdx.x * 256 + threadIdx.x;
    if (i >= HIDP * 512) return;
    int r = i / 512;
    float v = (r < HIDN) ? W[i] : 0.f;
    bf16 h, l; split2(v, h, l);
    hi[i] = h; lo[i] = l;
}

// ---------------- skinny projection: out[row,0..7] = A[row,:]@W (K=256) ----------------
__global__ void k_proj8(const float* __restrict__ A, const float* __restrict__ W,
                        float* __restrict__ out)
{
    __shared__ float Wsh[256 * 8];
    int t = threadIdx.x;
    for (int idx = t; idx < 2048; idx += 256) Wsh[idx] = W[idx];
    __syncthreads();
    int warp = t >> 5, lane = t & 31;
    long row = (long)blockIdx.x * 8 + warp;
    const float* a = A + row * 256;
    float acc[8] = {0.f,0.f,0.f,0.f,0.f,0.f,0.f,0.f};
    for (int kk = lane; kk < 256; kk += 32) {
        float av = a[kk];
        #pragma unroll
        for (int h = 0; h < 8; h++) acc[h] += av * Wsh[kk * 8 + h];
    }
    #pragma unroll
    for (int h = 0; h < 8; h++)
        #pragma unroll
        for (int off = 16; off; off >>= 1)
            acc[h] += __shfl_xor_sync(0xffffffffu, acc[h], off);
    if (lane == 0) {
        #pragma unroll
        for (int h = 0; h < 8; h++) out[row * 8 + h] = acc[h];
    }
}

// ---------------- edge / elementwise kernels ----------------
__global__ void k_zero(float* p, long n) {
    long i = (long)blockIdx.x * 256 + threadIdx.x;
    if (i < n) p[i] = 0.f;
}

__global__ void k_den1_init(const float* __restrict__ a_tgt, const float* __restrict__ b_attn,
                            float* __restrict__ den1) {
    int i = blockIdx.x * 256 + threadIdx.x;
    if (i >= NN * 8) return;
    float s = a_tgt[i] + b_attn[i & 7];
    s = s > 0.f ? s : 0.2f * s;
    den1[i] = expf(s);
}

__global__ void k_agg1_init(const float* __restrict__ root, const float* __restrict__ den1,
                            float* __restrict__ agg1) {
    long i = (long)blockIdx.x * 256 + threadIdx.x;
    long n = i >> 9; int c = (int)(i & 511);
    agg1[i] = den1[(n << 3) + (c >> 6)] * root[i];
}

__global__ void k_edge1_scores(const int* __restrict__ ej, const int* __restrict__ ei,
                               const float* __restrict__ a_src, const float* __restrict__ a_tgt,
                               const float* __restrict__ b_attn,
                               float* __restrict__ w1, float* __restrict__ den1) {
    int e = blockIdx.x * 256 + threadIdx.x;
    if (e >= E1N) return;
    int j = ej[e], i = ei[e];
    #pragma unroll
    for (int h = 0; h < 8; h++) {
        float s = a_src[j * 8 + h] + a_tgt[i * 8 + h] + b_attn[h];
        s = s > 0.f ? s : 0.2f * s;
        float w = expf(s);
        w1[e * 8 + h] = w;
        atomicAdd(&den1[i * 8 + h], w);
    }
}

__global__ void k_edge_scatter(const int* __restrict__ ej, const int* __restrict__ ei,
                               const float* __restrict__ w, const float* __restrict__ vals,
                               float* __restrict__ agg) {
    int e = blockIdx.x;
    int t = threadIdx.x;
    __shared__ float w8[8];
    __shared__ int sidx[2];
    if (t == 0) { sidx[0] = ej[e]; sidx[1] = ei[e]; }
    if (t < 8) w8[t] = w[e * 8 + t];
    __syncthreads();
    const float* src = vals + (size_t)sidx[0] * 512;
    float* dst = agg + (size_t)sidx[1] * 512;
    #pragma unroll
    for (int u2 = 0; u2 < 4; u2++) {
        int c = t + u2 * 128;
        atomicAdd(dst + c, w8[c >> 6] * src[c]);
    }
}

__global__ void k_edge2_scores(const float* __restrict__ q, const float* __restrict__ k,
                               const int* __restrict__ sj, const int* __restrict__ si,
                               const float* __restrict__ attr,
                               float* __restrict__ w2, float* __restrict__ den2) {
    int warp = (blockIdx.x * 256 + threadIdx.x) >> 5;
    int lane = threadIdx.x & 31;
    if (warp >= E2N) return;
    int jj = sj[warp], ii = si[warp];
    float a1 = attr[(size_t)warp * 64 + lane];
    float a2 = attr[(size_t)warp * 64 + 32 + lane];
    const float* qr = q + (size_t)ii * 512;
    const float* kr = k + (size_t)jj * 512;
    #pragma unroll
    for (int h = 0; h < 8; h++) {
        float p = qr[h * 64 + lane] * kr[h * 64 + lane] * a1
                + qr[h * 64 + 32 + lane] * kr[h * 64 + 32 + lane] * a2;
        #pragma unroll
        for (int off = 16; off; off >>= 1) p += __shfl_xor_sync(0xffffffffu, p, off);
        if (lane == 0) {
            float w = expf(p * 0.125f);
            w2[warp * 8 + h] = w;
            atomicAdd(&den2[ii * 8 + h], w);
        }
    }
}

// out = rmsnorm(base + (den ? num/den : num), g); optional bf16 hi/lo copies
__global__ void k_rmsnorm(const float* __restrict__ base, const float* __restrict__ num,
                          const float* __restrict__ den, const float* __restrict__ g,
                          float* __restrict__ out, bf16* __restrict__ oh, bf16* __restrict__ ol) {
    int n = blockIdx.x;
    int t = threadIdx.x;
    float v[4]; float ss = 0.f;
    #pragma unroll
    for (int u2 = 0; u2 < 4; u2++) {
        int c = t + u2 * 128;
        float a = num[(size_t)n * 512 + c];
        float add;
        if (den) { float d = den[n * 8 + (c >> 6)]; add = (d != 0.f) ? a / d : 0.f; }
        else add = a;
        float val = base[(size_t)n * 512 + c] + add;
        v[u2] = val; ss += val * val;
    }
    #pragma unroll
    for (int off = 16; off; off >>= 1) ss += __shfl_xor_sync(0xffffffffu, ss, off);
    __shared__ float red[4];
    if ((t & 31) == 0) red[t >> 5] = ss;
    __syncthreads();
    float tot = red[0] + red[1] + red[2] + red[3];
    float r = rsqrtf(tot * (1.0f / 512.0f) + 1e-6f);
    #pragma unroll
    for (int u2 = 0; u2 < 4; u2++) {
        int c = t + u2 * 128;
        float o = v[u2] * r * g[c];
        size_t idx = (size_t)n * 512 + c;
        out[idx] = o;
        if (oh) { bf16 h, l; split2(o, h, l); oh[idx] = h; ol[idx] = l; }
    }
}

__global__ void k_silu_bf(const float* __restrict__ g, const float* __restrict__ u,
                          bf16* __restrict__ oh, bf16* __restrict__ ol, long n4) {
    long i = (long)blockIdx.x * 256 + threadIdx.x;
    if (i >= n4) return;
    long idx = i * 4;
    float4 gv = ld4(g + idx);
    float4 uv = ld4(u + idx);
    float r[4];
    r[0] = gv.x / (1.f + expf(-gv.x)) * uv.x;
    r[1] = gv.y / (1.f + expf(-gv.y)) * uv.y;
    r[2] = gv.z / (1.f + expf(-gv.z)) * uv.z;
    r[3] = gv.w / (1.f + expf(-gv.w)) * uv.w;
    bf16 h[4], l[4];
    #pragma unroll
    for (int e = 0; e < 4; e++) split2(r[e], h[e], l[e]);
    *reinterpret_cast<uint64_t*>(oh + idx) = *reinterpret_cast<uint64_t*>(h);
    *reinterpret_cast<uint64_t*>(ol + idx) = *reinterpret_cast<uint64_t*>(l);
}

// ---------------- host ----------------
#define SYM(p, s) cudaGetSymbolAddress((void**)&(p), s)

extern "C" void kernel_launch(void* const* d_in, const int* in_sizes, int n_in,
                              void* d_out, int out_size) {
    (void)in_sizes; (void)n_in; (void)out_size;
    const float* root   = (const float*)d_in[0];
    const float* fb     = (const float*)d_in[1];
    const int*   fbi    = (const int*)d_in[2];
    const int*   e1j = fbi;       const int* e1i = fbi + E1N;
    const float* fmaps  = (const float*)d_in[3];
    const int*   r2f    = (const int*)d_in[4];
    const int*   rei    = (const int*)d_in[5];
    const int*   e2j = rei;       const int* e2i = rei + E2N;
    const float* attr   = (const float*)d_in[6];
    const float* W_c2x  = (const float*)d_in[7];
    const float* b_c2x  = (const float*)d_in[8];
    const float* W_x2c  = (const float*)d_in[9];
    const float* b_x2c  = (const float*)d_in[10];
    const float* W_attn = (const float*)d_in[11];
    const float* b_attn = (const float*)d_in[12];
    const float* W_qkv  = (const float*)d_in[13];
    const float* b_qkv  = (const float*)d_in[14];
    const float* W_gate = (const float*)d_in[15];
    const float* W_up   = (const float*)d_in[16];
    const float* W_out  = (const float*)d_in[17];
    const float* W_fr   = (const float*)d_in[18];
    const float* b_fr   = (const float*)d_in[19];
    const float* gn     = (const float*)d_in[20];
    const float* gr     = (const float*)d_in[21];
    const float* gf     = (const float*)d_in[22];

    float* outx = (float*)d_out;
    float* outf = outx + (size_t)NN * ENCD;

    float *p_root_ctx, *p_a_src, *p_a_tgt, *p_fb_vals, *p_w1, *p_den1, *p_agg1, *p_x1;
    float *p_q, *p_k, *p_v, *p_w2, *p_den2, *p_agg2, *p_x2, *p_gate, *p_up, *p_o;
    SYM(p_root_ctx, s_root_ctx); SYM(p_a_src, s_a_src); SYM(p_a_tgt, s_a_tgt);
    SYM(p_fb_vals, s_fb_vals);   SYM(p_w1, s_w1);       SYM(p_den1, s_den1);
    SYM(p_agg1, s_agg1);         SYM(p_x1, s_x1);
    SYM(p_q, s_q); SYM(p_k, s_k); SYM(p_v, s_v);
    SYM(p_w2, s_w2); SYM(p_den2, s_den2); SYM(p_agg2, s_agg2); SYM(p_x2, s_x2);
    SYM(p_gate, s_gate); SYM(p_up, s_up); SYM(p_o, s_o);

    bf16 *rbh,*rbl,*fbh,*fbl,*x1h,*x1l,*x2h,*x2l,*gsh,*gsl,*xfh,*xfl;
    bf16 *wxh,*wxl,*wch,*wcl,*wqh,*wql,*wgh,*wgl,*wuh,*wul,*woh,*wol,*wfh,*wfl;
    SYM(rbh, s_rbh); SYM(rbl, s_rbl); SYM(fbh, s_fbh); SYM(fbl, s_fbl);
    SYM(x1h, s_x1h); SYM(x1l, s_x1l); SYM(x2h, s_x2h); SYM(x2l, s_x2l);
    SYM(gsh, s_gsh); SYM(gsl, s_gsl); SYM(xfh, s_xfh); SYM(xfl, s_xfl);
    SYM(wxh, s_wxh); SYM(wxl, s_wxl); SYM(wch, s_wch); SYM(wcl, s_wcl);
    SYM(wqh, s_wqh); SYM(wql, s_wql); SYM(wgh, s_wgh); SYM(wgl, s_wgl);
    SYM(wuh, s_wuh); SYM(wul, s_wul); SYM(woh, s_woh); SYM(wol, s_wol);
    SYM(wfh, s_wfh); SYM(wfl, s_wfl);

    cudaFuncSetAttribute(hgemm<0,false>, cudaFuncAttributeMaxDynamicSharedMemorySize, SMEMB);
    cudaFuncSetAttribute(hgemm<1,false>, cudaFuncAttributeMaxDynamicSharedMemorySize, SMEMB);
    cudaFuncSetAttribute(hgemm<2,true>,  cudaFuncAttributeMaxDynamicSharedMemorySize, SMEMB);

    // ---- conversions (weights + inputs) ----
    k_split<<<(ENCD*DECD/4 + 255)/256, 256>>>(W_x2c, wxh, wxl, ENCD*DECD/4);
    k_split<<<(DECD*ENCD/4 + 255)/256, 256>>>(W_c2x, wch, wcl, DECD*ENCD/4);
    k_split<<<(ENCD*1536/4 + 255)/256, 256>>>(W_qkv, wqh, wql, ENCD*1536/4);
    k_split<<<(ENCD*DECD/4 + 255)/256, 256>>>(W_fr,  wfh, wfl, ENCD*DECD/4);
    k_split_padc<<<(512*HIDP + 255)/256, 256>>>(W_gate, wgh, wgl);
    k_split_padc<<<(512*HIDP + 255)/256, 256>>>(W_up,   wuh, wul);
    k_split_padr<<<(HIDP*512 + 255)/256, 256>>>(W_out,  woh, wol);
    k_split<<<((long)NN*ENCD/4 + 255)/256, 256>>>(root, rbh, rbl, (long)NN*ENCD/4);
    k_split<<<((long)MM*DECD/4 + 255)/256, 256>>>(fb,   fbh, fbl, (long)MM*DECD/4);

    // ---- HGAT pre-projections ----
    hgemm<0,false><<<dim3(2,128), 256, SMEMB>>>(rbh, rbl, wxh, wxl, b_x2c,
        p_root_ctx, nullptr, nullptr, nullptr, nullptr, DECD, ENCD);
    k_proj8<<<MM/8, 256>>>(fb, W_attn, p_a_src);
    k_proj8<<<NN/8, 256>>>(p_root_ctx, W_attn + 256*8, p_a_tgt);
    hgemm<0,false><<<dim3(4,512), 256, SMEMB>>>(fbh, fbl, wch, wcl, b_c2x,
        p_fb_vals, nullptr, nullptr, nullptr, nullptr, ENCD, DECD);

    // ---- HGAT edge softmax + aggregate ----
    k_den1_init<<<NN*8/256, 256>>>(p_a_tgt, b_attn, p_den1);
    k_agg1_init<<<NN*512/256, 256>>>(root, p_den1, p_agg1);
    k_edge1_scores<<<E1N/256, 256>>>(e1j, e1i, p_a_src, p_a_tgt, b_attn, p_w1, p_den1);
    k_edge_scatter<<<E1N, 128>>>(e1j, e1i, p_w1, p_fb_vals, p_agg1);
    k_rmsnorm<<<NN, 128>>>(root, p_agg1, p_den1, gn, p_x1, x1h, x1l);

    // ---- Self-MHA over root graph ----
    hgemm<1,false><<<dim3(12,128), 256, SMEMB>>>(x1h, x1l, wqh, wql, b_qkv,
        p_q, p_k, p_v, nullptr, nullptr, 1536, ENCD);
    k_zero<<<NN*8/256, 256>>>(p_den2, (long)NN*8);
    k_zero<<<NN*512/256, 256>>>(p_agg2, (long)NN*512);
    k_edge2_scores<<<E2N/8, 256>>>(p_q, p_k, e2j, e2i, attr, p_w2, p_den2);
    k_edge_scatter<<<E2N, 128>>>(e2j, e2i, p_w2, p_v, p_agg2);
    k_rmsnorm<<<NN, 128>>>(p_x1, p_agg2, p_den2, gr, p_x2, x2h, x2l);

    // ---- SwiGLU FFN ----
    hgemm<0,false><<<dim3(HIDP/128,128), 256, SMEMB>>>(x2h, x2l, wgh, wgl, nullptr,
        p_gate, nullptr, nullptr, nullptr, nullptr, HIDP, ENCD);
    hgemm<0,false><<<dim3(HIDP/128,128), 256, SMEMB>>>(x2h, x2l, wuh, wul, nullptr,
        p_up, nullptr, nullptr, nullptr, nullptr, HIDP, ENCD);
    k_silu_bf<<<(int)(((long)NN*HIDP/4 + 255)/256), 256>>>(p_gate, p_up, gsh, gsl,
        (long)NN*HIDP/4);
    hgemm<0,false><<<dim3(4,128), 256, SMEMB>>>(gsh, gsl, woh, wol, nullptr,
        p_o, nullptr, nullptr, nullptr, nullptr, ENCD, HIDP);
    k_rmsnorm<<<NN, 128>>>(p_x2, p_o, nullptr, gf, outx, xfh, xfl);

    // ---- fringe decode (gathered rows of x) ----
    hgemm<2,true><<<dim3(2,128), 256, SMEMB>>>(xfh, xfl, wfh, wfl, b_fr,
        outf, nullptr, nullptr, fmaps, r2f, DECD, ENCD);
}

// round 5
// speedup vs baseline: 2.4516x; 1.1297x over previous
#include <cuda_runtime.h>
#include <cuda_fp16.h>
#include <cstdint>
#include <math.h>

// ---------------- problem constants ----------------
#define NN   16384
#define MM   65536
#define E1N  131072
#define E2N  131072
#define ENCD 512
#define DECD 256
#define HCN  8
#define HIDN 1365
#define HIDP 1408

typedef __half f16;

// ---------------- fp32 scratch ----------------
static __device__ float s_root_ctx[NN * DECD];
static __device__ float s_a_src[MM * HCN];
static __device__ float s_a_tgt[NN * HCN];
static __device__ float s_fb_vals[(size_t)MM * ENCD];
static __device__ float s_w1[E1N * HCN];
static __device__ float s_den1[NN * HCN];
static __device__ float s_agg1[(size_t)NN * ENCD];
static __device__ float s_x1[(size_t)NN * ENCD];
static __device__ float s_q[(size_t)NN * ENCD];
static __device__ float s_k[(size_t)NN * ENCD];
static __device__ float s_v[(size_t)NN * ENCD];
static __device__ float s_w2[E2N * HCN];
static __device__ float s_den2[NN * HCN];
static __device__ float s_agg2[(size_t)NN * ENCD];
static __device__ float s_x2[(size_t)NN * ENCD];
static __device__ float s_gate[(size_t)NN * HIDP];
static __device__ float s_up[(size_t)NN * HIDP];
static __device__ float s_o[(size_t)NN * ENCD];

// ---------------- fp16 hi/lo scratch ----------------
static __device__ f16 s_rbh[(size_t)NN * ENCD],  s_rbl[(size_t)NN * ENCD];
static __device__ f16 s_fbh[(size_t)MM * DECD],  s_fbl[(size_t)MM * DECD];
static __device__ f16 s_x1h[(size_t)NN * ENCD],  s_x1l[(size_t)NN * ENCD];
static __device__ f16 s_x2h[(size_t)NN * ENCD],  s_x2l[(size_t)NN * ENCD];
static __device__ f16 s_gsh[(size_t)NN * HIDP],  s_gsl[(size_t)NN * HIDP];
static __device__ f16 s_xfh[(size_t)NN * ENCD],  s_xfl[(size_t)NN * ENCD];
// weights (hi always; lo only needed for qkv 3-term)
static __device__ f16 s_wxh[ENCD * DECD];
static __device__ f16 s_wch[DECD * ENCD];
static __device__ f16 s_wqh[ENCD * 1536],  s_wql[ENCD * 1536];
static __device__ f16 s_wgh[ENCD * HIDP];
static __device__ f16 s_wuh[ENCD * HIDP];
static __device__ f16 s_woh[HIDP * ENCD];
static __device__ f16 s_wfh[ENCD * DECD];

__device__ __forceinline__ float4 ld4(const float* p) {
    return *reinterpret_cast<const float4*>(p);
}

__device__ __forceinline__ void split2(float f, f16& h, f16& l) {
    h = __float2half_rn(f);
    l = __float2half_rn(f - __half2float(h));
}

// ================= baseline-PTX tensor helpers =================
__device__ __forceinline__ uint32_t smem_u32(const void* p) {
    uint32_t a;
    asm("{ .reg .u64 t; cvta.to.shared.u64 t, %1; cvt.u32.u64 %0, t; }" : "=r"(a) : "l"(p));
    return a;
}
#define CP16(dst, src) asm volatile("cp.async.cg.shared.global [%0], [%1], 16;" :: "r"(dst), "l"(src))
#define CP_COMMIT()    asm volatile("cp.async.commit_group;" ::: "memory")
#define CP_WAIT0()     asm volatile("cp.async.wait_group 0;" ::: "memory")

#define LDSMX4(r, a) \
    asm volatile("ldmatrix.sync.aligned.m8n8.x4.shared.b16 {%0,%1,%2,%3}, [%4];" \
        : "=r"((r)[0]), "=r"((r)[1]), "=r"((r)[2]), "=r"((r)[3]) : "r"(a))
#define LDSMX4T(r, a) \
    asm volatile("ldmatrix.sync.aligned.m8n8.x4.trans.shared.b16 {%0,%1,%2,%3}, [%4];" \
        : "=r"((r)[0]), "=r"((r)[1]), "=r"((r)[2]), "=r"((r)[3]) : "r"(a))

#define MMAH(d, a, b0, b1) \
    asm volatile("mma.sync.aligned.m16n8k16.row.col.f32.f16.f16.f32 " \
        "{%0,%1,%2,%3},{%4,%5,%6,%7},{%8,%9},{%0,%1,%2,%3};" \
        : "+f"((d)[0]), "+f"((d)[1]), "+f"((d)[2]), "+f"((d)[3]) \
        : "r"((a)[0]), "r"((a)[1]), "r"((a)[2]), "r"((a)[3]), "r"(b0), "r"(b1))

// smem per buffer: AH[128x80B] AL[128x80B] BH[32x272B] (BL[32x272B] iff TERMS==3)
#define SMEMB2 (2 * 29184)
#define SMEMB3 (2 * 37888)

// ============ split-fp16 HMMA GEMM: C = A@B (+bias) ============
// TERMS: 2 -> A_hi*B_hi + A_lo*B_hi (A exact, B fp16-rounded)
//        3 -> + A_hi*B_lo (B near-exact; for softmax-sensitive path)
// EPI: 0 plain, 1 qkv de-interleave, 2 fringe (*emul). GATHER: A row = rowidx[row].
template<int EPI, bool GATHER, int TERMS>
__global__ __launch_bounds__(256, (TERMS == 2 ? 2 : 1))
void hgemm(const f16* __restrict__ Ahi, const f16* __restrict__ Alo,
           const f16* __restrict__ Bhi, const f16* __restrict__ Blo,
           const float* __restrict__ bias,
           float* __restrict__ C0, float* __restrict__ C1, float* __restrict__ C2,
           const float* __restrict__ emul, const int* __restrict__ rowidx,
           int Nc, int K)
{
    constexpr uint32_t OFF_AL = 10240;
    constexpr uint32_t OFF_BH = 20480;
    constexpr uint32_t OFF_BL = 29184;                  // only valid when TERMS==3
    constexpr uint32_t BUFB   = (TERMS == 3) ? 37888u : 29184u;

    extern __shared__ __align__(16) char smc[];
    const uint32_t smb = smem_u32(smc);
    const int tid  = threadIdx.x;
    const int wid  = tid >> 5;
    const int lane = tid & 31;
    const int warp_m = wid >> 2;   // 0..1
    const int warp_n = wid & 3;    // 0..3
    const long bm = (long)blockIdx.y * 128;
    const long bn = (long)blockIdx.x * 128;

    long g0 = bm + (tid >> 2), g1 = g0 + 64;
    if (GATHER) {
        g0 = (long)rowidx[bm + (tid >> 2)];
        g1 = (long)rowidx[bm + (tid >> 2) + 64];
    }
    const f16* pAh0 = Ahi + g0 * (long)K + (tid & 3) * 8;
    const f16* pAl0 = Alo + g0 * (long)K + (tid & 3) * 8;
    const f16* pAh1 = Ahi + g1 * (long)K + (tid & 3) * 8;
    const f16* pAl1 = Alo + g1 * (long)K + (tid & 3) * 8;
    const f16* pBh  = Bhi + (long)(tid >> 4) * Nc + bn + (tid & 15) * 8;
    const f16* pBl  = (TERMS == 3) ? (Blo + (long)(tid >> 4) * Nc + bn + (tid & 15) * 8) : nullptr;

    const uint32_t dA  = (uint32_t)((tid >> 2) * 80 + (tid & 3) * 16);
    const uint32_t dA2 = dA + 64 * 80;
    const uint32_t dB  = (uint32_t)((tid >> 4) * 272 + (tid & 15) * 16);
    const uint32_t dB2 = dB + 16 * 272;

    float acc[4][4][4];
    #pragma unroll
    for (int a = 0; a < 4; a++)
        #pragma unroll
        for (int b = 0; b < 4; b++)
            #pragma unroll
            for (int c = 0; c < 4; c++) acc[a][b][c] = 0.f;

    const int nch = K >> 5;

    {
        const uint32_t base = smb;
        CP16(base + dA,            pAh0);
        CP16(base + OFF_AL + dA,   pAl0);
        CP16(base + dA2,           pAh1);
        CP16(base + OFF_AL + dA2,  pAl1);
        CP16(base + OFF_BH + dB,   pBh);
        CP16(base + OFF_BH + dB2,  pBh + 16L * Nc);
        if (TERMS == 3) {
            CP16(base + OFF_BL + dB,  pBl);
            CP16(base + OFF_BL + dB2, pBl + 16L * Nc);
        }
        CP_COMMIT();
    }

    for (int ch = 0; ch < nch; ch++) {
        CP_WAIT0();
        __syncthreads();
        if (ch + 1 < nch) {
            const int kt = (ch + 1) << 5;
            const uint32_t base = smb + ((ch + 1) & 1) * BUFB;
            CP16(base + dA,           pAh0 + kt);
            CP16(base + OFF_AL + dA,  pAl0 + kt);
            CP16(base + dA2,          pAh1 + kt);
            CP16(base + OFF_AL + dA2, pAl1 + kt);
            const f16* q0 = pBh + (long)kt * Nc;
            CP16(base + OFF_BH + dB,  q0);
            CP16(base + OFF_BH + dB2, q0 + 16L * Nc);
            if (TERMS == 3) {
                const f16* q1 = pBl + (long)kt * Nc;
                CP16(base + OFF_BL + dB,  q1);
                CP16(base + OFF_BL + dB2, q1 + 16L * Nc);
            }
            CP_COMMIT();
        }
        const uint32_t abase = smb + (ch & 1) * BUFB;
        const uint32_t bbase = abase + OFF_BH;

        #pragma unroll
        for (int ks = 0; ks < 2; ks++) {
            uint32_t ah[4][4], al[4][4];
            #pragma unroll
            for (int mt = 0; mt < 4; mt++) {
                uint32_t ad = abase
                    + (uint32_t)((warp_m * 64 + mt * 16 + (lane & 15)) * 80)
                    + (uint32_t)((ks * 16 + ((lane >> 4) << 3)) << 1);
                LDSMX4(ah[mt], ad);
                LDSMX4(al[mt], ad + OFF_AL);
            }
            uint32_t bh[2][4], bl[2][4];
            #pragma unroll
            for (int p = 0; p < 2; p++) {
                int kk = ks * 16 + (lane & 7) + ((lane >> 3) & 1) * 8;
                int nn = warp_n * 32 + p * 16 + ((lane >> 4) & 1) * 8;
                uint32_t bd = bbase + (uint32_t)(kk * 272 + nn * 2);
                LDSMX4T(bh[p], bd);
                if (TERMS == 3) LDSMX4T(bl[p], bd + (OFF_BL - OFF_BH));
            }
            #pragma unroll
            for (int mt = 0; mt < 4; mt++)
                #pragma unroll
                for (int nt = 0; nt < 4; nt++) {
                    const int p = nt >> 1, h = (nt & 1) * 2;
                    MMAH(acc[mt][nt], ah[mt], bh[p][h], bh[p][h + 1]);
                    MMAH(acc[mt][nt], al[mt], bh[p][h], bh[p][h + 1]);
                    if (TERMS == 3)
                        MMAH(acc[mt][nt], ah[mt], bl[p][h], bl[p][h + 1]);
                }
        }
        __syncthreads();
    }

    // ---- epilogue ----
    #pragma unroll
    for (int mt = 0; mt < 4; mt++) {
        #pragma unroll
        for (int nt = 0; nt < 4; nt++) {
            long r0 = bm + warp_m * 64 + mt * 16 + (lane >> 2);
            int  c0 = (int)bn + warp_n * 32 + nt * 8 + (lane & 3) * 2;
            #pragma unroll
            for (int half = 0; half < 2; half++) {
                long r = r0 + half * 8;
                float v0 = acc[mt][nt][half * 2 + 0];
                float v1 = acc[mt][nt][half * 2 + 1];
                if (bias) { v0 += bias[c0]; v1 += bias[c0 + 1]; }
                if (EPI == 1) {
                    #pragma unroll
                    for (int e = 0; e < 2; e++) {
                        int gc = c0 + e;
                        float vv = e ? v1 : v0;
                        int h = gc / 192, rr = gc % 192;
                        int d = rr / 3, t = rr % 3;
                        float* P = (t == 0) ? C0 : ((t == 1) ? C1 : C2);
                        P[r * 512 + h * 64 + d] = vv;
                    }
                } else {
                    if (EPI == 2) {
                        v0 *= emul[r * (long)Nc + c0];
                        v1 *= emul[r * (long)Nc + c0 + 1];
                    }
                    float2 o = make_float2(v0, v1);
                    *reinterpret_cast<float2*>(C0 + r * (long)Nc + c0) = o;
                }
            }
        }
    }
}

// ---------------- conversion kernels ----------------
__global__ void k_split(const float* __restrict__ in, f16* __restrict__ hi,
                        f16* __restrict__ lo, long n4) {
    long i = (long)blockIdx.x * 256 + threadIdx.x;
    if (i >= n4) return;
    long idx = i * 4;
    float4 v = ld4(in + idx);
    f16 h[4], l[4];
    split2(v.x, h[0], l[0]); split2(v.y, h[1], l[1]);
    split2(v.z, h[2], l[2]); split2(v.w, h[3], l[3]);
    *reinterpret_cast<uint64_t*>(hi + idx) = *reinterpret_cast<uint64_t*>(h);
    *reinterpret_cast<uint64_t*>(lo + idx) = *reinterpret_cast<uint64_t*>(l);
}

__global__ void k_hi(const float* __restrict__ in, f16* __restrict__ hi, long n4) {
    long i = (long)blockIdx.x * 256 + threadIdx.x;
    if (i >= n4) return;
    long idx = i * 4;
    float4 v = ld4(in + idx);
    f16 h[4];
    h[0] = __float2half_rn(v.x); h[1] = __float2half_rn(v.y);
    h[2] = __float2half_rn(v.z); h[3] = __float2half_rn(v.w);
    *reinterpret_cast<uint64_t*>(hi + idx) = *reinterpret_cast<uint64_t*>(h);
}

__global__ void k_hi_padc(const float* __restrict__ W, f16* __restrict__ hi) {
    int i = blockIdx.x * 256 + threadIdx.x;            // [512,1365] -> [512,1408]
    if (i >= 512 * HIDP) return;
    int r = i / HIDP, c = i % HIDP;
    hi[i] = __float2half_rn((c < HIDN) ? W[r * HIDN + c] : 0.f);
}

__global__ void k_hi_padr(const float* __restrict__ W, f16* __restrict__ hi) {
    int i = blockIdx.x * 256 + threadIdx.x;            // [1365,512] -> [1408,512]
    if (i >= HIDP * 512) return;
    int r = i / 512;
    hi[i] = __float2half_rn((r < HIDN) ? W[i] : 0.f);
}

// ---------------- skinny projection: out[row,0..7] = A[row,:]@W (K=256) ----------------
__global__ void k_proj8(const float* __restrict__ A, const float* __restrict__ W,
                        float* __restrict__ out)
{
    __shared__ float Wsh[256 * 8];
    int t = threadIdx.x;
    for (int idx = t; idx < 2048; idx += 256) Wsh[idx] = W[idx];
    __syncthreads();
    int warp = t >> 5, lane = t & 31;
    long row = (long)blockIdx.x * 8 + warp;
    const float* a = A + row * 256;
    float acc[8] = {0.f,0.f,0.f,0.f,0.f,0.f,0.f,0.f};
    for (int kk = lane; kk < 256; kk += 32) {
        float av = a[kk];
        #pragma unroll
        for (int h = 0; h < 8; h++) acc[h] += av * Wsh[kk * 8 + h];
    }
    #pragma unroll
    for (int h = 0; h < 8; h++)
        #pragma unroll
        for (int off = 16; off; off >>= 1)
            acc[h] += __shfl_xor_sync(0xffffffffu, acc[h], off);
    if (lane == 0) {
        #pragma unroll
        for (int h = 0; h < 8; h++) out[row * 8 + h] = acc[h];
    }
}

// ---------------- edge / elementwise kernels ----------------
__global__ void k_zero(float* p, long n) {
    long i = (long)blockIdx.x * 256 + threadIdx.x;
    if (i < n) p[i] = 0.f;
}

__global__ void k_den1_init(const float* __restrict__ a_tgt, const float* __restrict__ b_attn,
                            float* __restrict__ den1) {
    int i = blockIdx.x * 256 + threadIdx.x;
    if (i >= NN * 8) return;
    float s = a_tgt[i] + b_attn[i & 7];
    s = s > 0.f ? s : 0.2f * s;
    den1[i] = expf(s);
}

__global__ void k_agg1_init(const float* __restrict__ root, const float* __restrict__ den1,
                            float* __restrict__ agg1) {
    long i = (long)blockIdx.x * 256 + threadIdx.x;
    long n = i >> 9; int c = (int)(i & 511);
    agg1[i] = den1[(n << 3) + (c >> 6)] * root[i];
}

__global__ void k_edge1_scores(const int* __restrict__ ej, const int* __restrict__ ei,
                               const float* __restrict__ a_src, const float* __restrict__ a_tgt,
                               const float* __restrict__ b_attn,
                               float* __restrict__ w1, float* __restrict__ den1) {
    int e = blockIdx.x * 256 + threadIdx.x;
    if (e >= E1N) return;
    int j = ej[e], i = ei[e];
    #pragma unroll
    for (int h = 0; h < 8; h++) {
        float s = a_src[j * 8 + h] + a_tgt[i * 8 + h] + b_attn[h];
        s = s > 0.f ? s : 0.2f * s;
        float w = expf(s);
        w1[e * 8 + h] = w;
        atomicAdd(&den1[i * 8 + h], w);
    }
}

__global__ void k_edge_scatter(const int* __restrict__ ej, const int* __restrict__ ei,
                               const float* __restrict__ w, const float* __restrict__ vals,
                               float* __restrict__ agg) {
    int e = blockIdx.x;
    int t = threadIdx.x;
    __shared__ float w8[8];
    __shared__ int sidx[2];
    if (t == 0) { sidx[0] = ej[e]; sidx[1] = ei[e]; }
    if (t < 8) w8[t] = w[e * 8 + t];
    __syncthreads();
    const float* src = vals + (size_t)sidx[0] * 512;
    float* dst = agg + (size_t)sidx[1] * 512;
    #pragma unroll
    for (int u2 = 0; u2 < 4; u2++) {
        int c = t + u2 * 128;
        atomicAdd(dst + c, w8[c >> 6] * src[c]);
    }
}

__global__ void k_edge2_scores(const float* __restrict__ q, const float* __restrict__ k,
                               const int* __restrict__ sj, const int* __restrict__ si,
                               const float* __restrict__ attr,
                               float* __restrict__ w2, float* __restrict__ den2) {
    int warp = (blockIdx.x * 256 + threadIdx.x) >> 5;
    int lane = threadIdx.x & 31;
    if (warp >= E2N) return;
    int jj = sj[warp], ii = si[warp];
    float a1 = attr[(size_t)warp * 64 + lane];
    float a2 = attr[(size_t)warp * 64 + 32 + lane];
    const float* qr = q + (size_t)ii * 512;
    const float* kr = k + (size_t)jj * 512;
    #pragma unroll
    for (int h = 0; h < 8; h++) {
        float p = qr[h * 64 + lane] * kr[h * 64 + lane] * a1
                + qr[h * 64 + 32 + lane] * kr[h * 64 + 32 + lane] * a2;
        #pragma unroll
        for (int off = 16; off; off >>= 1) p += __shfl_xor_sync(0xffffffffu, p, off);
        if (lane == 0) {
            float w = expf(p * 0.125f);
            w2[warp * 8 + h] = w;
            atomicAdd(&den2[ii * 8 + h], w);
        }
    }
}

// out = rmsnorm(base + (den ? num/den : num), g); optional fp16 hi/lo copies
__global__ void k_rmsnorm(const float* __restrict__ base, const float* __restrict__ num,
                          const float* __restrict__ den, const float* __restrict__ g,
                          float* __restrict__ out, f16* __restrict__ oh, f16* __restrict__ ol) {
    int n = blockIdx.x;
    int t = threadIdx.x;
    float v[4]; float ss = 0.f;
    #pragma unroll
    for (int u2 = 0; u2 < 4; u2++) {
        int c = t + u2 * 128;
        float a = num[(size_t)n * 512 + c];
        float add;
        if (den) { float d = den[n * 8 + (c >> 6)]; add = (d != 0.f) ? a / d : 0.f; }
        else add = a;
        float val = base[(size_t)n * 512 + c] + add;
        v[u2] = val; ss += val * val;
    }
    #pragma unroll
    for (int off = 16; off; off >>= 1) ss += __shfl_xor_sync(0xffffffffu, ss, off);
    __shared__ float red[4];
    if ((t & 31) == 0) red[t >> 5] = ss;
    __syncthreads();
    float tot = red[0] + red[1] + red[2] + red[3];
    float r = rsqrtf(tot * (1.0f / 512.0f) + 1e-6f);
    #pragma unroll
    for (int u2 = 0; u2 < 4; u2++) {
        int c = t + u2 * 128;
        float o = v[u2] * r * g[c];
        size_t idx = (size_t)n * 512 + c;
        out[idx] = o;
        if (oh) { f16 h, l; split2(o, h, l); oh[idx] = h; ol[idx] = l; }
    }
}

__global__ void k_silu_f16(const float* __restrict__ g, const float* __restrict__ u,
                           f16* __restrict__ oh, f16* __restrict__ ol, long n4) {
    long i = (long)blockIdx.x * 256 + threadIdx.x;
    if (i >= n4) return;
    long idx = i * 4;
    float4 gv = ld4(g + idx);
    float4 uv = ld4(u + idx);
    float r[4];
    r[0] = gv.x / (1.f + expf(-gv.x)) * uv.x;
    r[1] = gv.y / (1.f + expf(-gv.y)) * uv.y;
    r[2] = gv.z / (1.f + expf(-gv.z)) * uv.z;
    r[3] = gv.w / (1.f + expf(-gv.w)) * uv.w;
    f16 h[4], l[4];
    #pragma unroll
    for (int e = 0; e < 4; e++) split2(r[e], h[e], l[e]);
    *reinterpret_cast<uint64_t*>(oh + idx) = *reinterpret_cast<uint64_t*>(h);
    *reinterpret_cast<uint64_t*>(ol + idx) = *reinterpret_cast<uint64_t*>(l);
}

// ---------------- host ----------------
#define SYM(p, s) cudaGetSymbolAddress((void**)&(p), s)

extern "C" void kernel_launch(void* const* d_in, const int* in_sizes, int n_in,
                              void* d_out, int out_size) {
    (void)in_sizes; (void)n_in; (void)out_size;
    const float* root   = (const float*)d_in[0];
    const float* fb     = (const float*)d_in[1];
    const int*   fbi    = (const int*)d_in[2];
    const int*   e1j = fbi;       const int* e1i = fbi + E1N;
    const float* fmaps  = (const float*)d_in[3];
    const int*   r2f    = (const int*)d_in[4];
    const int*   rei    = (const int*)d_in[5];
    const int*   e2j = rei;       const int* e2i = rei + E2N;
    const float* attr   = (const float*)d_in[6];
    const float* W_c2x  = (const float*)d_in[7];
    const float* b_c2x  = (const float*)d_in[8];
    const float* W_x2c  = (const float*)d_in[9];
    const float* b_x2c  = (const float*)d_in[10];
    const float* W_attn = (const float*)d_in[11];
    const float* b_attn = (const float*)d_in[12];
    const float* W_qkv  = (const float*)d_in[13];
    const float* b_qkv  = (const float*)d_in[14];
    const float* W_gate = (const float*)d_in[15];
    const float* W_up   = (const float*)d_in[16];
    const float* W_out  = (const float*)d_in[17];
    const float* W_fr   = (const float*)d_in[18];
    const float* b_fr   = (const float*)d_in[19];
    const float* gn     = (const float*)d_in[20];
    const float* gr     = (const float*)d_in[21];
    const float* gf     = (const float*)d_in[22];

    float* outx = (float*)d_out;
    float* outf = outx + (size_t)NN * ENCD;

    float *p_root_ctx, *p_a_src, *p_a_tgt, *p_fb_vals, *p_w1, *p_den1, *p_agg1, *p_x1;
    float *p_q, *p_k, *p_v, *p_w2, *p_den2, *p_agg2, *p_x2, *p_gate, *p_up, *p_o;
    SYM(p_root_ctx, s_root_ctx); SYM(p_a_src, s_a_src); SYM(p_a_tgt, s_a_tgt);
    SYM(p_fb_vals, s_fb_vals);   SYM(p_w1, s_w1);       SYM(p_den1, s_den1);
    SYM(p_agg1, s_agg1);         SYM(p_x1, s_x1);
    SYM(p_q, s_q); SYM(p_k, s_k); SYM(p_v, s_v);
    SYM(p_w2, s_w2); SYM(p_den2, s_den2); SYM(p_agg2, s_agg2); SYM(p_x2, s_x2);
    SYM(p_gate, s_gate); SYM(p_up, s_up); SYM(p_o, s_o);

    f16 *rbh,*rbl,*fbh,*fbl,*x1h,*x1l,*x2h,*x2l,*gsh,*gsl,*xfh,*xfl;
    f16 *wxh,*wch,*wqh,*wql,*wgh,*wuh,*woh,*wfh;
    SYM(rbh, s_rbh); SYM(rbl, s_rbl); SYM(fbh, s_fbh); SYM(fbl, s_fbl);
    SYM(x1h, s_x1h); SYM(x1l, s_x1l); SYM(x2h, s_x2h); SYM(x2l, s_x2l);
    SYM(gsh, s_gsh); SYM(gsl, s_gsl); SYM(xfh, s_xfh); SYM(xfl, s_xfl);
    SYM(wxh, s_wxh); SYM(wch, s_wch); SYM(wqh, s_wqh); SYM(wql, s_wql);
    SYM(wgh, s_wgh); SYM(wuh, s_wuh); SYM(woh, s_woh); SYM(wfh, s_wfh);

    cudaFuncSetAttribute((const void*)hgemm<0,false,2>, cudaFuncAttributeMaxDynamicSharedMemorySize, SMEMB2);
    cudaFuncSetAttribute((const void*)hgemm<1,false,3>, cudaFuncAttributeMaxDynamicSharedMemorySize, SMEMB3);
    cudaFuncSetAttribute((const void*)hgemm<2,true,2>,  cudaFuncAttributeMaxDynamicSharedMemorySize, SMEMB2);

    // ---- conversions ----
    k_hi<<<(ENCD*DECD/4 + 255)/256, 256>>>(W_x2c, wxh, ENCD*DECD/4);
    k_hi<<<(DECD*ENCD/4 + 255)/256, 256>>>(W_c2x, wch, DECD*ENCD/4);
    k_split<<<(ENCD*1536/4 + 255)/256, 256>>>(W_qkv, wqh, wql, ENCD*1536/4);
    k_hi<<<(ENCD*DECD/4 + 255)/256, 256>>>(W_fr, wfh, ENCD*DECD/4);
    k_hi_padc<<<(512*HIDP + 255)/256, 256>>>(W_gate, wgh);
    k_hi_padc<<<(512*HIDP + 255)/256, 256>>>(W_up,   wuh);
    k_hi_padr<<<(HIDP*512 + 255)/256, 256>>>(W_out,  woh);
    k_split<<<((long)NN*ENCD/4 + 255)/256, 256>>>(root, rbh, rbl, (long)NN*ENCD/4);
    k_split<<<((long)MM*DECD/4 + 255)/256, 256>>>(fb,   fbh, fbl, (long)MM*DECD/4);

    // ---- HGAT pre-projections ----
    hgemm<0,false,2><<<dim3(2,128), 256, SMEMB2>>>(rbh, rbl, wxh, nullptr, b_x2c,
        p_root_ctx, nullptr, nullptr, nullptr, nullptr, DECD, ENCD);
    k_proj8<<<MM/8, 256>>>(fb, W_attn, p_a_src);
    k_proj8<<<NN/8, 256>>>(p_root_ctx, W_attn + 256*8, p_a_tgt);
    hgemm<0,false,2><<<dim3(4,512), 256, SMEMB2>>>(fbh, fbl, wch, nullptr, b_c2x,
        p_fb_vals, nullptr, nullptr, nullptr, nullptr, ENCD, DECD);

    // ---- HGAT edge softmax + aggregate ----
    k_den1_init<<<NN*8/256, 256>>>(p_a_tgt, b_attn, p_den1);
    k_agg1_init<<<NN*512/256, 256>>>(root, p_den1, p_agg1);
    k_edge1_scores<<<E1N/256, 256>>>(e1j, e1i, p_a_src, p_a_tgt, b_attn, p_w1, p_den1);
    k_edge_scatter<<<E1N, 128>>>(e1j, e1i, p_w1, p_fb_vals, p_agg1);
    k_rmsnorm<<<NN, 128>>>(root, p_agg1, p_den1, gn, p_x1, x1h, x1l);

    // ---- Self-MHA (qkv: 3-term, softmax-sensitive) ----
    hgemm<1,false,3><<<dim3(12,128), 256, SMEMB3>>>(x1h, x1l, wqh, wql, b_qkv,
        p_q, p_k, p_v, nullptr, nullptr, 1536, ENCD);
    k_zero<<<NN*8/256, 256>>>(p_den2, (long)NN*8);
    k_zero<<<NN*512/256, 256>>>(p_agg2, (long)NN*512);
    k_edge2_scores<<<E2N/8, 256>>>(p_q, p_k, e2j, e2i, attr, p_w2, p_den2);
    k_edge_scatter<<<E2N, 128>>>(e2j, e2i, p_w2, p_v, p_agg2);
    k_rmsnorm<<<NN, 128>>>(p_x1, p_agg2, p_den2, gr, p_x2, x2h, x2l);

    // ---- SwiGLU FFN ----
    hgemm<0,false,2><<<dim3(HIDP/128,128), 256, SMEMB2>>>(x2h, x2l, wgh, nullptr, nullptr,
        p_gate, nullptr, nullptr, nullptr, nullptr, HIDP, ENCD);
    hgemm<0,false,2><<<dim3(HIDP/128,128), 256, SMEMB2>>>(x2h, x2l, wuh, nullptr, nullptr,
        p_up, nullptr, nullptr, nullptr, nullptr, HIDP, ENCD);
    k_silu_f16<<<(int)(((long)NN*HIDP/4 + 255)/256), 256>>>(p_gate, p_up, gsh, gsl,
        (long)NN*HIDP/4);
    hgemm<0,false,2><<<dim3(4,128), 256, SMEMB2>>>(gsh, gsl, woh, nullptr, nullptr,
        p_o, nullptr, nullptr, nullptr, nullptr, ENCD, HIDP);
    k_rmsnorm<<<NN, 128>>>(p_x2, p_o, nullptr, gf, outx, xfh, xfl);

    // ---- fringe decode ----
    hgemm<2,true,2><<<dim3(2,128), 256, SMEMB2>>>(xfh, xfl, wfh, nullptr, b_fr,
        outf, nullptr, nullptr, fmaps, r2f, DECD, ENCD);
}